// round 16
// baseline (speedup 1.0000x reference)
#include <cuda_runtime.h>
#include <cstdint>

#define NN 20000
#define EO 640000
#define EP (EO + NN)
#define CD 128
#define GG 64
#define NEGS 0.2f
#define L2E 1.4426950408889634f

// ---------------- persistent scratch (static __device__, no allocs) ----------
__device__ int    g_flags[2];          // [0]: edge_index is int64, [1]: batch is int64
__device__ int    g_deg[NN + 32];      // padded for int4 tail
__device__ int    g_rowptr[NN + 32];   // g_rowptr[n] = segment start; [NN] = EP
__device__ int    g_cursor[NN + 32];
__device__ int    g_srcA[EP + 8];      // +8 pad: clamp-free prefetch
__device__ float4 g_eaA[EP + 8];       // +8 pad (zeroed)
__device__ float  g_xl[NN * CD];
__device__ float  g_xr[NN * CD];
__device__ float  g_h[NN * CD];
__device__ float  g_pool[GG * CD];
__device__ int    g_gcnt[GG];

__device__ __forceinline__ int ld_idx(const void* p, long long i, int f64) {
    if (f64) return (int)(((const long long*)p)[i]);
    return ((const int*)p)[i];
}

__device__ __forceinline__ uint32_t f2tf32(float x) {
    uint32_t r;
    asm("cvt.rna.tf32.f32 %0, %1;" : "=r"(r) : "f"(x));
    return r;
}

__device__ __forceinline__ float ex2(float x) {
    float r;
    asm("ex2.approx.f32 %0, %1;" : "=f"(r) : "f"(x));
    return r;
}

// ---------------- zero + dtype detection fused --------------------------------
__global__ void k_zero(const int* ei, const int* bat) {
    int i = blockIdx.x * blockDim.x + threadIdx.x;
    if (i == 0) {
        // If int64 storage, odd int32 positions are high words == 0.
        g_flags[0] = (ei[2LL * EO - 1] == 0 && ei[2LL * EO - 3] == 0) ? 1 : 0;
        g_flags[1] = (bat[NN - 1] == 0) ? 1 : 0;
    }
    if (i < 8) {                        // pad slots: finite, masked out in attn
        g_srcA[EP + i] = 0;
        g_eaA[EP + i] = make_float4(0.f, 0.f, 0.f, 0.f);
    }
    int stride = gridDim.x * blockDim.x;
    for (int j = i; j < NN + 32; j += stride) g_deg[j] = 0;
    for (int j = i; j < GG * CD; j += stride) g_pool[j] = 0.f;
    for (int j = i; j < GG; j += stride) g_gcnt[j] = 0;
}

// degree per destination (1 atomic/edge; measured best)
__global__ void k_deg(const void* __restrict__ ei) {
    int f = g_flags[0];
    int e = blockIdx.x * blockDim.x + threadIdx.x;
    if (e < EO) {
        int dst = ld_idx(ei, (long long)EO + e, f);
        atomicAdd(&g_deg[dst], 1);
    }
}

// single-block vectorized scan: counts = deg+1 (self loop reserved last).
__global__ void __launch_bounds__(1024) k_scan() {
    __shared__ int warpsum[32];
    const int PER = 20;                 // 1000 threads * 20 == NN exactly
    int t = threadIdx.x;
    int lane = t & 31, wid = t >> 5;
    int base = t * PER;
    bool live = (base < NN);            // threads 0..999

    int v[PER];
    int sum = 0;
    if (live) {
        const int4* dp = (const int4*)(g_deg + base);
#pragma unroll
        for (int i = 0; i < 5; i++) {
            int4 d = dp[i];
            v[4 * i + 0] = d.x + 1;
            v[4 * i + 1] = d.y + 1;
            v[4 * i + 2] = d.z + 1;
            v[4 * i + 3] = d.w + 1;
        }
#pragma unroll
        for (int i = 0; i < PER; i++) { int tv = v[i]; v[i] = sum; sum += tv; }
    }
    int x = sum;
#pragma unroll
    for (int d = 1; d < 32; d <<= 1) {
        int y = __shfl_up_sync(0xffffffffu, x, d);
        if (lane >= d) x += y;
    }
    if (lane == 31) warpsum[wid] = x;
    __syncthreads();
    if (wid == 0) {
        int y = warpsum[lane];
#pragma unroll
        for (int d = 1; d < 32; d <<= 1) {
            int z = __shfl_up_sync(0xffffffffu, y, d);
            if (lane >= d) y += z;
        }
        warpsum[lane] = y;
    }
    __syncthreads();
    int offset = ((wid > 0) ? warpsum[wid - 1] : 0) + (x - sum);

    if (live) {
        int4* cp = (int4*)(g_cursor + base);
        int4* rp = (int4*)(g_rowptr + base);
#pragma unroll
        for (int i = 0; i < 5; i++) {
            int4 o;
            o.x = offset + v[4 * i + 0];
            o.y = offset + v[4 * i + 1];
            o.z = offset + v[4 * i + 2];
            o.w = offset + v[4 * i + 3];
            cp[i] = o;
            rp[i] = o;
        }
    }
    if (t == 0) g_rowptr[NN] = EP;
}

// scatter real edges into CSR order; self-loop slot (last) left open
__global__ void k_scatter(const void* __restrict__ ei, const float* __restrict__ eattr) {
    int f = g_flags[0];
    int e = blockIdx.x * blockDim.x + threadIdx.x;
    if (e < EO) {
        int s = ld_idx(ei, e, f);
        int d = ld_idx(ei, (long long)EO + e, f);
        float4 a = ((const float4*)eattr)[e];
        int pos = atomicAdd(&g_cursor[d], 1);
        g_srcA[pos] = s;
        g_eaA[pos] = a;
    }
}

// warp per node: segment-mean edge_attr -> fill self-loop slot (no atomics)
__global__ void __launch_bounds__(256) k_selfloop() {
    int w = threadIdx.x >> 5;
    int lane = threadIdx.x & 31;
    int n = blockIdx.x * 8 + w;
    if (n >= NN) return;
    int beg = g_rowptr[n];
    int endr = g_rowptr[n + 1] - 1;
    float4 s = make_float4(0.f, 0.f, 0.f, 0.f);
    for (int i = beg + lane; i < endr; i += 32) {
        float4 a = g_eaA[i];
        s.x += a.x; s.y += a.y; s.z += a.z; s.w += a.w;
    }
#pragma unroll
    for (int o = 16; o > 0; o >>= 1) {
        s.x += __shfl_xor_sync(0xffffffffu, s.x, o);
        s.y += __shfl_xor_sync(0xffffffffu, s.y, o);
        s.z += __shfl_xor_sync(0xffffffffu, s.z, o);
        s.w += __shfl_xor_sync(0xffffffffu, s.w, o);
    }
    if (lane == 0) {
        int dg = endr - beg;
        float inv = 1.f / fmaxf((float)dg, 1.f);
        float4 m = make_float4(s.x * inv, s.y * inv, s.z * inv, s.w * inv);
        g_srcA[endr] = n;
        g_eaA[endr] = m;
    }
}

// ---------------- tf32 tensor-core dual GEMM (single wave, BM=144) -----------
__global__ void __launch_bounds__(576) k_gemm2(const float* __restrict__ in_ext,
                                               int din,
                                               const float* __restrict__ Wl,
                                               const float* __restrict__ bl,
                                               const float* __restrict__ Wr,
                                               const float* __restrict__ br) {
    __shared__ uint32_t As[8][152];         // stride 152 (mod 32 = 24): conflict-free frags
    __shared__ uint32_t Bs[32][8][8];       // [tile][k][n-in-tile]
    const float* in = in_ext ? in_ext : g_h;

    int t = threadIdx.x;
    int lane = t & 31;
    int w = t >> 5;
    int nbase = blockIdx.x * 144;
    int wrow = (w >> 1) * 16;               // 0..128
    int wtile = (w & 1) * 16;               // warp's first n-tile (of 32)

    float c[16][4];
#pragma unroll
    for (int i = 0; i < 16; i++)
#pragma unroll
        for (int j = 0; j < 4; j++) c[i][j] = 0.f;

    for (int kk = 0; kk < din; kk += 8) {
        {
            int r = t >> 2;                 // 0..143
            int kp = (t & 3) * 2;           // 0,2,4,6
            float2 av = make_float2(0.f, 0.f);
            if (nbase + r < NN)
                av = *(const float2*)&in[(size_t)(nbase + r) * din + kk + kp];
            As[kp][r] = f2tf32(av.x);
            As[kp + 1][r] = f2tf32(av.y);
        }
        {
            uint32_t* bflat = &Bs[0][0][0];
#pragma unroll
            for (int j = 0; j < 4; j++) {
                int idx = j * 576 + t;      // 0..2303
                if (idx < 2048) {
                    int k1 = (idx >> 3) & 7;
                    int col = ((idx >> 6) << 3) | (idx & 7);  // tile*8 + n
                    const float* Wp = (col < 128) ? Wl : Wr;
                    bflat[idx] = f2tf32(Wp[(size_t)(kk + k1) * CD + (col & 127)]);
                }
            }
        }
        __syncthreads();

        int ar = wrow + (lane >> 2);
        int ak = lane & 3;
        uint32_t a0 = As[ak][ar];
        uint32_t a1 = As[ak][ar + 8];
        uint32_t a2 = As[ak + 4][ar];
        uint32_t a3 = As[ak + 4][ar + 8];

#pragma unroll
        for (int ti = 0; ti < 16; ti++) {
            uint32_t b0 = Bs[wtile + ti][lane & 3][lane >> 2];
            uint32_t b1 = Bs[wtile + ti][(lane & 3) + 4][lane >> 2];
            asm volatile(
                "mma.sync.aligned.m16n8k8.row.col.f32.tf32.tf32.f32 "
                "{%0,%1,%2,%3}, {%4,%5,%6,%7}, {%8,%9}, {%0,%1,%2,%3};"
                : "+f"(c[ti][0]), "+f"(c[ti][1]), "+f"(c[ti][2]), "+f"(c[ti][3])
                : "r"(a0), "r"(a1), "r"(a2), "r"(a3), "r"(b0), "r"(b1));
        }
        __syncthreads();
    }

    int row0 = nbase + wrow + (lane >> 2);
    int row1 = row0 + 8;
#pragma unroll
    for (int ti = 0; ti < 16; ti++) {
        int col = (wtile + ti) * 8 + (lane & 3) * 2;   // 0..255
        bool isL = (col < 128);
        int cc = col & 127;
        const float* bp = isL ? bl : br;
        float* dst = isL ? g_xl : g_xr;
        float b0v = bp[cc], b1v = bp[cc + 1];
        if (row0 < NN) {
            float2 o = make_float2(c[ti][0] + b0v, c[ti][1] + b1v);
            *(float2*)&dst[(size_t)row0 * CD + cc] = o;
        }
        if (row1 < NN) {
            float2 o = make_float2(c[ti][2] + b0v, c[ti][3] + b1v);
            *(float2*)&dst[(size_t)row1 * CD + cc] = o;
        }
    }
}

// ---------------- GATv2 attention: warp per node, ILP-2, depth-2 pipeline ----
// Each iteration: issue gathers for pair k+1 (addresses prefetched last iter),
// load indices for pair k+2, compute pair k. Load->use distance = one full
// iteration. Padded arrays make all reads clamp-free; masking exact (ex2->0).
__global__ void __launch_bounds__(128) k_attn(const float* __restrict__ We,
                                              const float* __restrict__ att,
                                              const float* __restrict__ bias,
                                              int relu) {
    int w = threadIdx.x >> 5;
    int l = threadIdx.x & 31;
    int n = blockIdx.x * 4 + w;        // grid = 5000 -> exactly NN warps

    const float4* __restrict__ xl4 = (const float4*)g_xl;
    const float4* __restrict__ xr4 = (const float4*)g_xr;

    float4 xrd = xr4[n * 32 + l];
    float4 av = ((const float4*)att)[l];
    av.x *= L2E; av.y *= L2E; av.z *= L2E; av.w *= L2E;   // exp2 domain
    float4 w0 = ((const float4*)We)[0 * 32 + l];
    float4 w1 = ((const float4*)We)[1 * 32 + l];
    float4 w2 = ((const float4*)We)[2 * 32 + l];
    float4 w3 = ((const float4*)We)[3 * 32 + l];

    float m = -1e30f;
    float ssum = 0.f;
    float4 acc = make_float4(0.f, 0.f, 0.f, 0.f);

    int beg = __ldg(&g_rowptr[n]);
    int end = __ldg(&g_rowptr[n + 1]);

    // pipeline prologue: pair 0 values + pair 1 indices
    int s0 = g_srcA[beg];
    int s1 = g_srcA[beg + 1];
    float4 xls0 = xl4[s0 * 32 + l];
    float4 xls1 = xl4[s1 * 32 + l];
    float4 ea0 = g_eaA[beg];
    float4 ea1 = g_eaA[beg + 1];
    s0 = g_srcA[beg + 2];
    s1 = g_srcA[beg + 3];

    for (int e = beg; e < end; e += 2) {
        // issue gathers for NEXT pair (addresses already in regs)
        float4 xls2 = xl4[s0 * 32 + l];
        float4 xls3 = xl4[s1 * 32 + l];
        float4 ea2 = g_eaA[e + 2];
        float4 ea3 = g_eaA[e + 3];
        // prefetch indices for pair after next (pad-safe up to end+3 < EP+8)
        s0 = g_srcA[e + 4];
        s1 = g_srcA[e + 5];

        // compute CURRENT pair (values loaded one iteration ago)
        float4 m0, m1;
        m0.x = xls0.x + xrd.x + ea0.x * w0.x + ea0.y * w1.x + ea0.z * w2.x + ea0.w * w3.x;
        m0.y = xls0.y + xrd.y + ea0.x * w0.y + ea0.y * w1.y + ea0.z * w2.y + ea0.w * w3.y;
        m0.z = xls0.z + xrd.z + ea0.x * w0.z + ea0.y * w1.z + ea0.z * w2.z + ea0.w * w3.z;
        m0.w = xls0.w + xrd.w + ea0.x * w0.w + ea0.y * w1.w + ea0.z * w2.w + ea0.w * w3.w;
        m1.x = xls1.x + xrd.x + ea1.x * w0.x + ea1.y * w1.x + ea1.z * w2.x + ea1.w * w3.x;
        m1.y = xls1.y + xrd.y + ea1.x * w0.y + ea1.y * w1.y + ea1.z * w2.y + ea1.w * w3.y;
        m1.z = xls1.z + xrd.z + ea1.x * w0.z + ea1.y * w1.z + ea1.z * w2.z + ea1.w * w3.z;
        m1.w = xls1.w + xrd.w + ea1.x * w0.w + ea1.y * w1.w + ea1.z * w2.w + ea1.w * w3.w;

        float4 sv0, sv1;
        sv0.x = fmaxf(m0.x, NEGS * m0.x); sv0.y = fmaxf(m0.y, NEGS * m0.y);
        sv0.z = fmaxf(m0.z, NEGS * m0.z); sv0.w = fmaxf(m0.w, NEGS * m0.w);
        sv1.x = fmaxf(m1.x, NEGS * m1.x); sv1.y = fmaxf(m1.y, NEGS * m1.y);
        sv1.z = fmaxf(m1.z, NEGS * m1.z); sv1.w = fmaxf(m1.w, NEGS * m1.w);

        float p0 = sv0.x * av.x + sv0.y * av.y + sv0.z * av.z + sv0.w * av.w;
        float p1 = sv1.x * av.x + sv1.y * av.y + sv1.z * av.z + sv1.w * av.w;
        p0 += __shfl_xor_sync(0xffffffffu, p0, 1);
        p1 += __shfl_xor_sync(0xffffffffu, p1, 1);
        p0 += __shfl_xor_sync(0xffffffffu, p0, 2);
        p1 += __shfl_xor_sync(0xffffffffu, p1, 2);
        p0 += __shfl_xor_sync(0xffffffffu, p0, 4);
        p1 += __shfl_xor_sync(0xffffffffu, p1, 4);

        if (e + 1 >= end) p1 = -1e30f;  // ex2 -> 0 exactly

        float nm = fmaxf(m, fmaxf(p0, p1));
        float scale = ex2(m - nm);
        float w0e = ex2(p0 - nm);
        float w1e = ex2(p1 - nm);
        ssum = ssum * scale + w0e + w1e;
        acc.x = acc.x * scale + w0e * xls0.x + w1e * xls1.x;
        acc.y = acc.y * scale + w0e * xls0.y + w1e * xls1.y;
        acc.z = acc.z * scale + w0e * xls0.z + w1e * xls1.z;
        acc.w = acc.w * scale + w0e * xls0.w + w1e * xls1.w;
        m = nm;

        // rotate pipeline
        xls0 = xls2; xls1 = xls3; ea0 = ea2; ea1 = ea3;
    }

    float inv = 1.f / (ssum + 1e-16f);
    float4 bb = ((const float4*)bias)[l];
    float4 o;
    o.x = acc.x * inv + bb.x;
    o.y = acc.y * inv + bb.y;
    o.z = acc.z * inv + bb.z;
    o.w = acc.w * inv + bb.w;
    if (relu) {
        o.x = fmaxf(o.x, 0.f);
        o.y = fmaxf(o.y, 0.f);
        o.z = fmaxf(o.z, 0.f);
        o.w = fmaxf(o.w, 0.f);
    }
    ((float4*)g_h)[n * 32 + l] = o;
}

// ---------------- global mean pool (batch sorted) ----------------------------
__global__ void k_pool(const void* __restrict__ bat) {
    int c = threadIdx.x;               // 128 threads = channels
    int f = g_flags[1];
    int n0 = blockIdx.x * 64;
    int n1 = min(n0 + 64, NN);
    int cg = ld_idx(bat, n0, f);
    float sum = 0.f;
    int cnt = 0;
    for (int i = n0; i < n1; ++i) {
        int g = ld_idx(bat, i, f);
        if (g != cg) {
            atomicAdd(&g_pool[cg * CD + c], sum);
            if (c == 0) atomicAdd(&g_gcnt[cg], cnt);
            sum = 0.f;
            cnt = 0;
            cg = g;
        }
        sum += g_h[(long long)i * CD + c];
        cnt++;
    }
    atomicAdd(&g_pool[cg * CD + c], sum);
    if (c == 0) atomicAdd(&g_gcnt[cg], cnt);
}

__global__ void k_final(float* __restrict__ out) {
    int i = blockIdx.x * blockDim.x + threadIdx.x;
    if (i < GG * CD) {
        out[i] = g_pool[i] / fmaxf((float)g_gcnt[i >> 7], 1.f);
    }
}

// ---------------- launch ----------------------------------------------------
extern "C" void kernel_launch(void* const* d_in, const int* in_sizes, int n_in,
                              void* d_out, int out_size) {
    const float* x     = (const float*)d_in[0];
    const float* eattr = (const float*)d_in[1];
    const void*  ei    = d_in[2];
    const void*  bat   = d_in[3];

    const float* Wl[3]; const float* bl[3];
    const float* Wr[3]; const float* br[3];
    const float* We[3]; const float* at[3]; const float* bi[3];
    for (int L = 0; L < 3; ++L) {
        int base = 4 + 7 * L;
        Wl[L] = (const float*)d_in[base + 0];
        bl[L] = (const float*)d_in[base + 1];
        Wr[L] = (const float*)d_in[base + 2];
        br[L] = (const float*)d_in[base + 3];
        We[L] = (const float*)d_in[base + 4];
        at[L] = (const float*)d_in[base + 5];
        bi[L] = (const float*)d_in[base + 6];
    }

    const int gemm_blocks = (NN + 143) / 144;   // 139 -> single wave

    k_zero<<<64, 256>>>((const int*)ei, (const int*)bat);
    k_deg<<<(EO + 255) / 256, 256>>>(ei);
    k_scan<<<1, 1024>>>();
    // Layer-1 GEMM in 4th launch slot (only depends on x) -> gets profiled.
    k_gemm2<<<gemm_blocks, 576>>>(x, 16, Wl[0], bl[0], Wr[0], br[0]);
    k_scatter<<<(EO + 255) / 256, 256>>>(ei, eattr);
    k_selfloop<<<(NN + 7) / 8, 256>>>();

    // Layer 1 attention, relu after
    k_attn<<<NN / 4, 128>>>(We[0], at[0], bi[0], 1);
    // Layer 2, relu after
    k_gemm2<<<gemm_blocks, 576>>>(nullptr, 128, Wl[1], bl[1], Wr[1], br[1]);
    k_attn<<<NN / 4, 128>>>(We[1], at[1], bi[1], 1);
    // Layer 3, no relu
    k_gemm2<<<gemm_blocks, 576>>>(nullptr, 128, Wl[2], bl[2], Wr[2], br[2]);
    k_attn<<<NN / 4, 128>>>(We[2], at[2], bi[2], 0);

    k_pool<<<(NN + 63) / 64, 128>>>(bat);
    k_final<<<(GG * CD + 255) / 256, 256>>>((float*)d_out);
}

// round 17
// speedup vs baseline: 1.0684x; 1.0684x over previous
#include <cuda_runtime.h>
#include <cstdint>

#define NN 20000
#define EO 640000
#define EP (EO + NN)
#define CD 128
#define GG 64
#define NEGS 0.2f
#define L2E 1.4426950408889634f

// ---------------- persistent scratch (static __device__, no allocs) ----------
__device__ int    g_flags[2];          // [0]: edge_index is int64, [1]: batch is int64
__device__ int    g_deg[NN + 32];      // padded for int4 tail
__device__ int    g_rowptr[NN + 32];   // g_rowptr[n] = segment start; [NN] = EP
__device__ int    g_cursor[NN + 32];
__device__ int    g_srcA[EP + 8];      // +8 pad: clamp-free prefetch
__device__ float4 g_eaA[EP + 8];       // +8 pad (zeroed)
__device__ float  g_xl[NN * CD];
__device__ float  g_xr[NN * CD];
__device__ float  g_h[NN * CD];
__device__ float  g_pool[GG * CD];
__device__ int    g_gcnt[GG];

__device__ __forceinline__ int ld_idx(const void* p, long long i, int f64) {
    if (f64) return (int)(((const long long*)p)[i]);
    return ((const int*)p)[i];
}

__device__ __forceinline__ uint32_t f2tf32(float x) {
    uint32_t r;
    asm("cvt.rna.tf32.f32 %0, %1;" : "=r"(r) : "f"(x));
    return r;
}

__device__ __forceinline__ float ex2(float x) {
    float r;
    asm("ex2.approx.f32 %0, %1;" : "=f"(r) : "f"(x));
    return r;
}

// ---------------- zero + dtype detection fused --------------------------------
__global__ void k_zero(const int* ei, const int* bat) {
    int i = blockIdx.x * blockDim.x + threadIdx.x;
    if (i == 0) {
        // If int64 storage, odd int32 positions are high words == 0.
        g_flags[0] = (ei[2LL * EO - 1] == 0 && ei[2LL * EO - 3] == 0) ? 1 : 0;
        g_flags[1] = (bat[NN - 1] == 0) ? 1 : 0;
    }
    if (i < 8) {                        // pad slots: finite, masked out in attn
        g_srcA[EP + i] = 0;
        g_eaA[EP + i] = make_float4(0.f, 0.f, 0.f, 0.f);
    }
    int stride = gridDim.x * blockDim.x;
    for (int j = i; j < NN + 32; j += stride) g_deg[j] = 0;
    for (int j = i; j < GG * CD; j += stride) g_pool[j] = 0.f;
    for (int j = i; j < GG; j += stride) g_gcnt[j] = 0;
}

// degree per destination (1 atomic/edge; measured best)
__global__ void k_deg(const void* __restrict__ ei) {
    int f = g_flags[0];
    int e = blockIdx.x * blockDim.x + threadIdx.x;
    if (e < EO) {
        int dst = ld_idx(ei, (long long)EO + e, f);
        atomicAdd(&g_deg[dst], 1);
    }
}

// single-block vectorized scan: counts = deg+1 (self loop reserved last).
__global__ void __launch_bounds__(1024) k_scan() {
    __shared__ int warpsum[32];
    const int PER = 20;                 // 1000 threads * 20 == NN exactly
    int t = threadIdx.x;
    int lane = t & 31, wid = t >> 5;
    int base = t * PER;
    bool live = (base < NN);            // threads 0..999

    int v[PER];
    int sum = 0;
    if (live) {
        const int4* dp = (const int4*)(g_deg + base);
#pragma unroll
        for (int i = 0; i < 5; i++) {
            int4 d = dp[i];
            v[4 * i + 0] = d.x + 1;
            v[4 * i + 1] = d.y + 1;
            v[4 * i + 2] = d.z + 1;
            v[4 * i + 3] = d.w + 1;
        }
#pragma unroll
        for (int i = 0; i < PER; i++) { int tv = v[i]; v[i] = sum; sum += tv; }
    }
    int x = sum;
#pragma unroll
    for (int d = 1; d < 32; d <<= 1) {
        int y = __shfl_up_sync(0xffffffffu, x, d);
        if (lane >= d) x += y;
    }
    if (lane == 31) warpsum[wid] = x;
    __syncthreads();
    if (wid == 0) {
        int y = warpsum[lane];
#pragma unroll
        for (int d = 1; d < 32; d <<= 1) {
            int z = __shfl_up_sync(0xffffffffu, y, d);
            if (lane >= d) y += z;
        }
        warpsum[lane] = y;
    }
    __syncthreads();
    int offset = ((wid > 0) ? warpsum[wid - 1] : 0) + (x - sum);

    if (live) {
        int4* cp = (int4*)(g_cursor + base);
        int4* rp = (int4*)(g_rowptr + base);
#pragma unroll
        for (int i = 0; i < 5; i++) {
            int4 o;
            o.x = offset + v[4 * i + 0];
            o.y = offset + v[4 * i + 1];
            o.z = offset + v[4 * i + 2];
            o.w = offset + v[4 * i + 3];
            cp[i] = o;
            rp[i] = o;
        }
    }
    if (t == 0) g_rowptr[NN] = EP;
}

// scatter real edges into CSR order; self-loop slot (last) left open
__global__ void k_scatter(const void* __restrict__ ei, const float* __restrict__ eattr) {
    int f = g_flags[0];
    int e = blockIdx.x * blockDim.x + threadIdx.x;
    if (e < EO) {
        int s = ld_idx(ei, e, f);
        int d = ld_idx(ei, (long long)EO + e, f);
        float4 a = ((const float4*)eattr)[e];
        int pos = atomicAdd(&g_cursor[d], 1);
        g_srcA[pos] = s;
        g_eaA[pos] = a;
    }
}

// warp per node: segment-mean edge_attr -> fill self-loop slot (no atomics)
__global__ void __launch_bounds__(256) k_selfloop() {
    int w = threadIdx.x >> 5;
    int lane = threadIdx.x & 31;
    int n = blockIdx.x * 8 + w;
    if (n >= NN) return;
    int beg = g_rowptr[n];
    int endr = g_rowptr[n + 1] - 1;
    float4 s = make_float4(0.f, 0.f, 0.f, 0.f);
    for (int i = beg + lane; i < endr; i += 32) {
        float4 a = g_eaA[i];
        s.x += a.x; s.y += a.y; s.z += a.z; s.w += a.w;
    }
#pragma unroll
    for (int o = 16; o > 0; o >>= 1) {
        s.x += __shfl_xor_sync(0xffffffffu, s.x, o);
        s.y += __shfl_xor_sync(0xffffffffu, s.y, o);
        s.z += __shfl_xor_sync(0xffffffffu, s.z, o);
        s.w += __shfl_xor_sync(0xffffffffu, s.w, o);
    }
    if (lane == 0) {
        int dg = endr - beg;
        float inv = 1.f / fmaxf((float)dg, 1.f);
        float4 m = make_float4(s.x * inv, s.y * inv, s.z * inv, s.w * inv);
        g_srcA[endr] = n;
        g_eaA[endr] = m;
    }
}

// ---------------- tf32 tensor-core dual GEMM (single wave, double-buffered) --
// BM=144, 576 threads, 139 blocks = 1 wave. Global->register staging for the
// NEXT k-iter issues right after the smem write barrier, overlapping the 16
// MMAs + epilogue sync of the CURRENT iter (global loads were previously fully
// exposed inside the serial k-loop: tensor 4.6%, ~700cy/iter of bare latency).
__global__ void __launch_bounds__(576) k_gemm2(const float* __restrict__ in_ext,
                                               int din,
                                               const float* __restrict__ Wl,
                                               const float* __restrict__ bl,
                                               const float* __restrict__ Wr,
                                               const float* __restrict__ br) {
    __shared__ uint32_t As[8][152];         // stride 152 (mod 32 = 24): conflict-free frags
    __shared__ uint32_t Bs[32][8][8];       // [tile][k][n-in-tile]
    const float* in = in_ext ? in_ext : g_h;

    int t = threadIdx.x;
    int lane = t & 31;
    int w = t >> 5;
    int nbase = blockIdx.x * 144;
    int wrow = (w >> 1) * 16;               // 0..128
    int wtile = (w & 1) * 16;               // warp's first n-tile (of 32)

    // per-thread fill coordinates (fixed across k-iters)
    int r = t >> 2;                         // A row 0..143
    int kp = (t & 3) * 2;                   // A k-pair 0,2,4,6
    bool rowok = (nbase + r < NN);
    const float* arow = in + (size_t)(nbase + r) * din + kp;

    // B fill coords: idx = j*576 + t -> [k1][col]
    int bk1[4]; const float* bptr[4]; bool bok[4]; int bidx[4];
#pragma unroll
    for (int j = 0; j < 4; j++) {
        int idx = j * 576 + t;
        bok[j] = (idx < 2048);
        bidx[j] = idx;
        int k1 = (idx >> 3) & 7;
        int col = ((idx >> 6) << 3) | (idx & 7);
        bk1[j] = k1;
        bptr[j] = ((col < 128) ? Wl : Wr) + (col & 127);
    }

    float c[16][4];
#pragma unroll
    for (int i = 0; i < 16; i++)
#pragma unroll
        for (int j = 0; j < 4; j++) c[i][j] = 0.f;

    // prologue: stage k=0
    float2 av = rowok ? *(const float2*)arow : make_float2(0.f, 0.f);
    float bv[4];
#pragma unroll
    for (int j = 0; j < 4; j++)
        bv[j] = bok[j] ? bptr[j][(size_t)bk1[j] * CD] : 0.f;

    uint32_t* bflat = &Bs[0][0][0];

    for (int kk = 0; kk < din; kk += 8) {
        // commit staged registers to smem
        As[kp][r] = f2tf32(av.x);
        As[kp + 1][r] = f2tf32(av.y);
#pragma unroll
        for (int j = 0; j < 4; j++)
            if (bok[j]) bflat[bidx[j]] = f2tf32(bv[j]);
        __syncthreads();

        // stage NEXT iteration's globals (overlaps MMAs below)
        if (kk + 8 < din) {
            av = rowok ? *(const float2*)(arow + kk + 8) : make_float2(0.f, 0.f);
#pragma unroll
            for (int j = 0; j < 4; j++)
                bv[j] = bok[j] ? bptr[j][(size_t)(kk + 8 + bk1[j]) * CD] : 0.f;
        }

        // MMAs from smem
        int ar = wrow + (lane >> 2);
        int ak = lane & 3;
        uint32_t a0 = As[ak][ar];
        uint32_t a1 = As[ak][ar + 8];
        uint32_t a2 = As[ak + 4][ar];
        uint32_t a3 = As[ak + 4][ar + 8];

#pragma unroll
        for (int ti = 0; ti < 16; ti++) {
            uint32_t b0 = Bs[wtile + ti][lane & 3][lane >> 2];
            uint32_t b1 = Bs[wtile + ti][(lane & 3) + 4][lane >> 2];
            asm volatile(
                "mma.sync.aligned.m16n8k8.row.col.f32.tf32.tf32.f32 "
                "{%0,%1,%2,%3}, {%4,%5,%6,%7}, {%8,%9}, {%0,%1,%2,%3};"
                : "+f"(c[ti][0]), "+f"(c[ti][1]), "+f"(c[ti][2]), "+f"(c[ti][3])
                : "r"(a0), "r"(a1), "r"(a2), "r"(a3), "r"(b0), "r"(b1));
        }
        __syncthreads();
    }

    int row0 = nbase + wrow + (lane >> 2);
    int row1 = row0 + 8;
#pragma unroll
    for (int ti = 0; ti < 16; ti++) {
        int col = (wtile + ti) * 8 + (lane & 3) * 2;   // 0..255
        bool isL = (col < 128);
        int cc = col & 127;
        const float* bp = isL ? bl : br;
        float* dst = isL ? g_xl : g_xr;
        float b0v = bp[cc], b1v = bp[cc + 1];
        if (row0 < NN) {
            float2 o = make_float2(c[ti][0] + b0v, c[ti][1] + b1v);
            *(float2*)&dst[(size_t)row0 * CD + cc] = o;
        }
        if (row1 < NN) {
            float2 o = make_float2(c[ti][2] + b0v, c[ti][3] + b1v);
            *(float2*)&dst[(size_t)row1 * CD + cc] = o;
        }
    }
}

// ---------------- GATv2 attention (R15 form — measured best; do not touch) ---
// 128-thread blocks, ILP-2, clamp-free prefetch via padded arrays, exp2-domain
// softmax with online max.
__global__ void __launch_bounds__(128) k_attn(const float* __restrict__ We,
                                              const float* __restrict__ att,
                                              const float* __restrict__ bias,
                                              int relu) {
    int w = threadIdx.x >> 5;
    int l = threadIdx.x & 31;
    int n = blockIdx.x * 4 + w;        // grid = 5000 -> exactly NN warps

    const float4* __restrict__ xl4 = (const float4*)g_xl;
    const float4* __restrict__ xr4 = (const float4*)g_xr;

    float4 xrd = xr4[n * 32 + l];
    float4 av = ((const float4*)att)[l];
    av.x *= L2E; av.y *= L2E; av.z *= L2E; av.w *= L2E;   // exp2 domain
    float4 w0 = ((const float4*)We)[0 * 32 + l];
    float4 w1 = ((const float4*)We)[1 * 32 + l];
    float4 w2 = ((const float4*)We)[2 * 32 + l];
    float4 w3 = ((const float4*)We)[3 * 32 + l];

    float m = -1e30f;
    float ssum = 0.f;
    float4 acc = make_float4(0.f, 0.f, 0.f, 0.f);

    int beg = __ldg(&g_rowptr[n]);
    int end = __ldg(&g_rowptr[n + 1]);

    int s0 = g_srcA[beg];
    int s1 = g_srcA[beg + 1];

    for (int e = beg; e < end; e += 2) {
        float4 xls0 = xl4[s0 * 32 + l];
        float4 xls1 = xl4[s1 * 32 + l];
        float4 ea0 = g_eaA[e];
        float4 ea1 = g_eaA[e + 1];
        s0 = g_srcA[e + 2];
        s1 = g_srcA[e + 3];

        float4 m0, m1;
        m0.x = xls0.x + xrd.x + ea0.x * w0.x + ea0.y * w1.x + ea0.z * w2.x + ea0.w * w3.x;
        m0.y = xls0.y + xrd.y + ea0.x * w0.y + ea0.y * w1.y + ea0.z * w2.y + ea0.w * w3.y;
        m0.z = xls0.z + xrd.z + ea0.x * w0.z + ea0.y * w1.z + ea0.z * w2.z + ea0.w * w3.z;
        m0.w = xls0.w + xrd.w + ea0.x * w0.w + ea0.y * w1.w + ea0.z * w2.w + ea0.w * w3.w;
        m1.x = xls1.x + xrd.x + ea1.x * w0.x + ea1.y * w1.x + ea1.z * w2.x + ea1.w * w3.x;
        m1.y = xls1.y + xrd.y + ea1.x * w0.y + ea1.y * w1.y + ea1.z * w2.y + ea1.w * w3.y;
        m1.z = xls1.z + xrd.z + ea1.x * w0.z + ea1.y * w1.z + ea1.z * w2.z + ea1.w * w3.z;
        m1.w = xls1.w + xrd.w + ea1.x * w0.w + ea1.y * w1.w + ea1.z * w2.w + ea1.w * w3.w;

        float4 sv0, sv1;
        sv0.x = fmaxf(m0.x, NEGS * m0.x); sv0.y = fmaxf(m0.y, NEGS * m0.y);
        sv0.z = fmaxf(m0.z, NEGS * m0.z); sv0.w = fmaxf(m0.w, NEGS * m0.w);
        sv1.x = fmaxf(m1.x, NEGS * m1.x); sv1.y = fmaxf(m1.y, NEGS * m1.y);
        sv1.z = fmaxf(m1.z, NEGS * m1.z); sv1.w = fmaxf(m1.w, NEGS * m1.w);

        float p0 = sv0.x * av.x + sv0.y * av.y + sv0.z * av.z + sv0.w * av.w;
        float p1 = sv1.x * av.x + sv1.y * av.y + sv1.z * av.z + sv1.w * av.w;
        p0 += __shfl_xor_sync(0xffffffffu, p0, 1);
        p1 += __shfl_xor_sync(0xffffffffu, p1, 1);
        p0 += __shfl_xor_sync(0xffffffffu, p0, 2);
        p1 += __shfl_xor_sync(0xffffffffu, p1, 2);
        p0 += __shfl_xor_sync(0xffffffffu, p0, 4);
        p1 += __shfl_xor_sync(0xffffffffu, p1, 4);

        if (e + 1 >= end) p1 = -1e30f;  // ex2 -> 0 exactly

        float nm = fmaxf(m, fmaxf(p0, p1));
        float scale = ex2(m - nm);
        float w0e = ex2(p0 - nm);
        float w1e = ex2(p1 - nm);
        ssum = ssum * scale + w0e + w1e;
        acc.x = acc.x * scale + w0e * xls0.x + w1e * xls1.x;
        acc.y = acc.y * scale + w0e * xls0.y + w1e * xls1.y;
        acc.z = acc.z * scale + w0e * xls0.z + w1e * xls1.z;
        acc.w = acc.w * scale + w0e * xls0.w + w1e * xls1.w;
        m = nm;
    }

    float inv = 1.f / (ssum + 1e-16f);
    float4 bb = ((const float4*)bias)[l];
    float4 o;
    o.x = acc.x * inv + bb.x;
    o.y = acc.y * inv + bb.y;
    o.z = acc.z * inv + bb.z;
    o.w = acc.w * inv + bb.w;
    if (relu) {
        o.x = fmaxf(o.x, 0.f);
        o.y = fmaxf(o.y, 0.f);
        o.z = fmaxf(o.z, 0.f);
        o.w = fmaxf(o.w, 0.f);
    }
    ((float4*)g_h)[n * 32 + l] = o;
}

// ---------------- global mean pool (batch sorted) ----------------------------
__global__ void k_pool(const void* __restrict__ bat) {
    int c = threadIdx.x;               // 128 threads = channels
    int f = g_flags[1];
    int n0 = blockIdx.x * 64;
    int n1 = min(n0 + 64, NN);
    int cg = ld_idx(bat, n0, f);
    float sum = 0.f;
    int cnt = 0;
    for (int i = n0; i < n1; ++i) {
        int g = ld_idx(bat, i, f);
        if (g != cg) {
            atomicAdd(&g_pool[cg * CD + c], sum);
            if (c == 0) atomicAdd(&g_gcnt[cg], cnt);
            sum = 0.f;
            cnt = 0;
            cg = g;
        }
        sum += g_h[(long long)i * CD + c];
        cnt++;
    }
    atomicAdd(&g_pool[cg * CD + c], sum);
    if (c == 0) atomicAdd(&g_gcnt[cg], cnt);
}

__global__ void k_final(float* __restrict__ out) {
    int i = blockIdx.x * blockDim.x + threadIdx.x;
    if (i < GG * CD) {
        out[i] = g_pool[i] / fmaxf((float)g_gcnt[i >> 7], 1.f);
    }
}

// ---------------- launch ----------------------------------------------------
extern "C" void kernel_launch(void* const* d_in, const int* in_sizes, int n_in,
                              void* d_out, int out_size) {
    const float* x     = (const float*)d_in[0];
    const float* eattr = (const float*)d_in[1];
    const void*  ei    = d_in[2];
    const void*  bat   = d_in[3];

    const float* Wl[3]; const float* bl[3];
    const float* Wr[3]; const float* br[3];
    const float* We[3]; const float* at[3]; const float* bi[3];
    for (int L = 0; L < 3; ++L) {
        int base = 4 + 7 * L;
        Wl[L] = (const float*)d_in[base + 0];
        bl[L] = (const float*)d_in[base + 1];
        Wr[L] = (const float*)d_in[base + 2];
        br[L] = (const float*)d_in[base + 3];
        We[L] = (const float*)d_in[base + 4];
        at[L] = (const float*)d_in[base + 5];
        bi[L] = (const float*)d_in[base + 6];
    }

    const int gemm_blocks = (NN + 143) / 144;   // 139 -> single wave

    k_zero<<<64, 256>>>((const int*)ei, (const int*)bat);
    k_deg<<<(EO + 255) / 256, 256>>>(ei);
    k_scan<<<1, 1024>>>();
    // Layer-1 GEMM in 4th launch slot (only depends on x) -> gets profiled.
    k_gemm2<<<gemm_blocks, 576>>>(x, 16, Wl[0], bl[0], Wr[0], br[0]);
    k_scatter<<<(EO + 255) / 256, 256>>>(ei, eattr);
    k_selfloop<<<(NN + 7) / 8, 256>>>();

    // Layer 1 attention, relu after
    k_attn<<<NN / 4, 128>>>(We[0], at[0], bi[0], 1);
    // Layer 2, relu after
    k_gemm2<<<gemm_blocks, 576>>>(nullptr, 128, Wl[1], bl[1], Wr[1], br[1]);
    k_attn<<<NN / 4, 128>>>(We[1], at[1], bi[1], 1);
    // Layer 3, no relu
    k_gemm2<<<gemm_blocks, 576>>>(nullptr, 128, Wl[2], bl[2], Wr[2], br[2]);
    k_attn<<<NN / 4, 128>>>(We[2], at[2], bi[2], 0);

    k_pool<<<(NN + 63) / 64, 128>>>(bat);
    k_final<<<(GG * CD + 255) / 256, 256>>>((float*)d_out);
}